// round 4
// baseline (speedup 1.0000x reference)
#include <cuda_runtime.h>
#include <cstdint>

// Fused causal single-head attention, one CTA per batch element.
// B=4096, T=96, C=256, H=64.  tf32 mma.sync (m16n8k8), fp32 accumulate.
//
// Phase 1: qkv = x @ [Wq|Wk|Wv]   (x tile in smem, W streamed in k-chunks via cp.async)
// Phase 2: wei = (q @ k^T) * C^-0.5, causal mask, softmax   (all in smem/regs)
// Phase 3: out = wei @ v -> gmem
//
// 384 threads = 12 warps. Phase-1 warp tile: m32 x n48 (3 row-groups x 4 col-quarters).

namespace {
constexpr int Tq = 96;
constexpr int Cd = 256;
constexpr int Hd = 64;

// padded smem strides (floats) chosen for conflict-free fragment access
constexpr int XS_STRIDE = 260;   // bank = (4*row + col) % 32
constexpr int WC_STRIDE = 200;   // bank = (8*krow + col) % 32
constexpr int QS_STRIDE = 68;
constexpr int KS_STRIDE = 68;
constexpr int VS_STRIDE = 72;    // bank = (8*s + col) % 32
constexpr int WS_STRIDE = 100;

// phase-1 smem layout (floats)
constexpr int XS_OFF  = 0;
constexpr int WC0_OFF = Tq * XS_STRIDE;             // 24960
constexpr int WC1_OFF = WC0_OFF + 64 * WC_STRIDE;   // 37760
constexpr int SMEM_FLOATS = WC1_OFF + 64 * WC_STRIDE; // 50560 -> 202240 B

// phase-2 overlay (xs/Wc dead by then)
constexpr int QS_OFF = 0;
constexpr int KS_OFF = QS_OFF + Tq * QS_STRIDE;     // 6528
constexpr int VS_OFF = KS_OFF + Tq * KS_STRIDE;     // 13056
constexpr int WS_OFF = VS_OFF + Tq * VS_STRIDE;     // 19968 (ends 29568 < 50560)

constexpr int SMEM_BYTES = SMEM_FLOATS * 4;
}

__device__ __forceinline__ float tf32r(float f) {
    // round-to-nearest tf32, kept as an fp32 bit pattern (low 13 bits zero)
    uint32_t u;
    asm("cvt.rna.tf32.f32 %0, %1;" : "=r"(u) : "f"(f));
    return __uint_as_float(u);
}

__device__ __forceinline__ void mma_tf32(float* acc, const uint32_t* a, const uint32_t* b) {
    asm volatile(
        "mma.sync.aligned.m16n8k8.row.col.f32.tf32.tf32.f32 "
        "{%0,%1,%2,%3}, {%4,%5,%6,%7}, {%8,%9}, {%0,%1,%2,%3};"
        : "+f"(acc[0]), "+f"(acc[1]), "+f"(acc[2]), "+f"(acc[3])
        : "r"(a[0]), "r"(a[1]), "r"(a[2]), "r"(a[3]), "r"(b[0]), "r"(b[1]));
}

__device__ __forceinline__ void cp16(float* smem_dst, const float* gsrc) {
    uint32_t s = (uint32_t)__cvta_generic_to_shared(smem_dst);
    asm volatile("cp.async.cg.shared.global [%0], [%1], 16;" :: "r"(s), "l"(gsrc));
}
#define CP_COMMIT() asm volatile("cp.async.commit_group;")
#define CP_WAIT(n)  asm volatile("cp.async.wait_group %0;" :: "n"(n))

__global__ __launch_bounds__(384, 1)
void head_attn_kernel(const float* __restrict__ x,
                      const float* __restrict__ Wk,
                      const float* __restrict__ Wq,
                      const float* __restrict__ Wv,
                      float* __restrict__ out) {
    extern __shared__ float sm[];
    const int b    = blockIdx.x;
    const int tid  = threadIdx.x;
    const int wid  = tid >> 5;
    const int lane = tid & 31;
    const int g    = lane >> 2;   // groupID (row within fragment)
    const int tg   = lane & 3;    // thread-in-group (col within fragment)

    const int mtp  = wid >> 2;    // 0..2 -> rows [mtp*32, mtp*32+32)
    const int nq   = wid & 3;     // 0..3 -> phase-dependent n quarter
    const int rowA0 = mtp * 32;

    const float* xb = x + (size_t)b * Tq * Cd;

    // ---------- async load: full x tile (96x256) ----------
    for (int i = tid; i < Tq * (Cd / 4); i += 384) {
        int row = i >> 6;       // /64 float4 per row
        int c4  = i & 63;
        cp16(&sm[XS_OFF + row * XS_STRIDE + c4 * 4], xb + row * Cd + c4 * 4);
    }
    // W chunk loader: chunk kc covers k rows [kc*64, kc*64+64). cols: 0-63 q, 64-127 k, 128-191 v
    auto load_wc = [&](int kc, int bufoff) {
        for (int i = tid; i < 64 * 48; i += 384) {   // 48 float4 per k-row
            int row = i / 48;
            int seg = i % 48;
            int w   = seg >> 4;                      // 0=q,1=k,2=v
            int c4  = seg & 15;
            const float* src = (w == 0 ? Wq : (w == 1 ? Wk : Wv))
                               + (size_t)(kc * 64 + row) * Hd + c4 * 4;
            cp16(&sm[bufoff + row * WC_STRIDE + w * 64 + c4 * 4], src);
        }
    };
    load_wc(0, WC0_OFF);
    CP_COMMIT();                 // group 0 = xs + Wc0
    load_wc(1, WC1_OFF);
    CP_COMMIT();                 // group 1 = Wc1

    auto cvt_wc = [&](int bufoff) {
        for (int i = tid; i < 64 * WC_STRIDE; i += 384)
            sm[bufoff + i] = tf32r(sm[bufoff + i]);
    };

    CP_WAIT(1);                  // xs + Wc0 landed
    __syncthreads();
    for (int i = tid; i < Tq * XS_STRIDE; i += 384)   // round x to tf32 in place
        sm[XS_OFF + i] = tf32r(sm[XS_OFF + i]);
    cvt_wc(WC0_OFF);
    __syncthreads();

    // ---------- phase 1: qkv accumulation ----------
    float acc[2][6][4];
    #pragma unroll
    for (int mi = 0; mi < 2; mi++)
        #pragma unroll
        for (int nj = 0; nj < 6; nj++)
            #pragma unroll
            for (int r = 0; r < 4; r++) acc[mi][nj][r] = 0.0f;

    auto compute_chunk = [&](int bufoff, int kbase) {
        #pragma unroll
        for (int kk = 0; kk < 8; kk++) {
            uint32_t afrag[2][4];
            #pragma unroll
            for (int mi = 0; mi < 2; mi++) {
                const float* ap = &sm[XS_OFF + (rowA0 + mi * 16 + g) * XS_STRIDE
                                      + kbase + kk * 8 + tg];
                afrag[mi][0] = __float_as_uint(ap[0]);
                afrag[mi][1] = __float_as_uint(ap[8 * XS_STRIDE]);
                afrag[mi][2] = __float_as_uint(ap[4]);
                afrag[mi][3] = __float_as_uint(ap[8 * XS_STRIDE + 4]);
            }
            #pragma unroll
            for (int nj = 0; nj < 6; nj++) {
                const float* bp = &sm[bufoff + (kk * 8 + tg) * WC_STRIDE
                                      + nq * 48 + nj * 8 + g];
                uint32_t bfrag[2];
                bfrag[0] = __float_as_uint(bp[0]);
                bfrag[1] = __float_as_uint(bp[4 * WC_STRIDE]);
                mma_tf32(acc[0][nj], afrag[0], bfrag);
                mma_tf32(acc[1][nj], afrag[1], bfrag);
            }
        }
    };

    // chunk 0 (Wc0), prefetch chunk 2 into Wc0 after
    compute_chunk(WC0_OFF, 0);
    CP_WAIT(0); __syncthreads();          // Wc1 landed, everyone done with Wc0
    load_wc(2, WC0_OFF); CP_COMMIT();
    cvt_wc(WC1_OFF);
    __syncthreads();

    compute_chunk(WC1_OFF, 64);
    CP_WAIT(0); __syncthreads();
    load_wc(3, WC1_OFF); CP_COMMIT();
    cvt_wc(WC0_OFF);
    __syncthreads();

    compute_chunk(WC0_OFF, 128);
    CP_WAIT(0); __syncthreads();
    cvt_wc(WC1_OFF);
    __syncthreads();

    compute_chunk(WC1_OFF, 192);
    __syncthreads();    // xs dead; safe to overlay q/k/v/ws

    // ---------- scatter qkv accumulators to smem (tf32-rounded) ----------
    auto qkv_ptr = [&](int row, int n) -> float* {
        if (n < 64)  return &sm[QS_OFF + row * QS_STRIDE + n];
        if (n < 128) return &sm[KS_OFF + row * KS_STRIDE + (n - 64)];
        return &sm[VS_OFF + row * VS_STRIDE + (n - 128)];
    };
    #pragma unroll
    for (int mi = 0; mi < 2; mi++)
        #pragma unroll
        for (int nj = 0; nj < 6; nj++) {
            int n    = nq * 48 + nj * 8 + 2 * tg;
            int row0 = rowA0 + mi * 16 + g;
            *(float2*)qkv_ptr(row0, n) =
                make_float2(tf32r(acc[mi][nj][0]), tf32r(acc[mi][nj][1]));
            *(float2*)qkv_ptr(row0 + 8, n) =
                make_float2(tf32r(acc[mi][nj][2]), tf32r(acc[mi][nj][3]));
        }
    __syncthreads();

    // ---------- phase 2: wei = q @ k^T, scale, causal mask ----------
    float wacc[2][3][4];
    #pragma unroll
    for (int mi = 0; mi < 2; mi++)
        #pragma unroll
        for (int nj = 0; nj < 3; nj++)
            #pragma unroll
            for (int r = 0; r < 4; r++) wacc[mi][nj][r] = 0.0f;

    #pragma unroll
    for (int kk = 0; kk < 8; kk++) {
        uint32_t qa[2][4];
        #pragma unroll
        for (int mi = 0; mi < 2; mi++) {
            const float* ap = &sm[QS_OFF + (rowA0 + mi * 16 + g) * QS_STRIDE + kk * 8 + tg];
            qa[mi][0] = __float_as_uint(ap[0]);
            qa[mi][1] = __float_as_uint(ap[8 * QS_STRIDE]);
            qa[mi][2] = __float_as_uint(ap[4]);
            qa[mi][3] = __float_as_uint(ap[8 * QS_STRIDE + 4]);
        }
        #pragma unroll
        for (int nj = 0; nj < 3; nj++) {
            // B[k=h][n=s] = k_mat[s][h]; ks is [s][h] row-major
            const float* bp = &sm[KS_OFF + (nq * 24 + nj * 8 + g) * KS_STRIDE + kk * 8 + tg];
            uint32_t bfrag[2] = { __float_as_uint(bp[0]), __float_as_uint(bp[4]) };
            mma_tf32(wacc[0][nj], qa[0], bfrag);
            mma_tf32(wacc[1][nj], qa[1], bfrag);
        }
    }
    {
        const float scale = 0.0625f;  // C^-0.5
        #pragma unroll
        for (int mi = 0; mi < 2; mi++)
            #pragma unroll
            for (int nj = 0; nj < 3; nj++) {
                int n    = nq * 24 + nj * 8 + 2 * tg;
                int row0 = rowA0 + mi * 16 + g;
                float s00 = (n     <= row0) ? wacc[mi][nj][0] * scale : -1e30f;
                float s01 = (n + 1 <= row0) ? wacc[mi][nj][1] * scale : -1e30f;
                float s10 = (n     <= row0 + 8) ? wacc[mi][nj][2] * scale : -1e30f;
                float s11 = (n + 1 <= row0 + 8) ? wacc[mi][nj][3] * scale : -1e30f;
                *(float2*)&sm[WS_OFF + row0 * WS_STRIDE + n]       = make_float2(s00, s01);
                *(float2*)&sm[WS_OFF + (row0 + 8) * WS_STRIDE + n] = make_float2(s10, s11);
            }
    }
    __syncthreads();

    // ---------- softmax: warp w owns rows [8w, 8w+8); 4 lanes per row ----------
    {
        int r = wid * 8 + (lane >> 2);
        int i = lane & 3;
        float vb[24];
        float mx = -1e30f;
        #pragma unroll
        for (int j = 0; j < 24; j++) {
            vb[j] = sm[WS_OFF + r * WS_STRIDE + i + 4 * j];
            mx = fmaxf(mx, vb[j]);
        }
        mx = fmaxf(mx, __shfl_xor_sync(0xffffffffu, mx, 1));
        mx = fmaxf(mx, __shfl_xor_sync(0xffffffffu, mx, 2));
        float ssum = 0.0f;
        #pragma unroll
        for (int j = 0; j < 24; j++) {
            vb[j] = __expf(vb[j] - mx);
            ssum += vb[j];
        }
        ssum += __shfl_xor_sync(0xffffffffu, ssum, 1);
        ssum += __shfl_xor_sync(0xffffffffu, ssum, 2);
        float inv = 1.0f / ssum;
        #pragma unroll
        for (int j = 0; j < 24; j++)
            sm[WS_OFF + r * WS_STRIDE + i + 4 * j] = tf32r(vb[j] * inv);
    }
    __syncthreads();

    // ---------- phase 3: out = wei @ v ----------
    float oacc[2][2][4];
    #pragma unroll
    for (int mi = 0; mi < 2; mi++)
        #pragma unroll
        for (int nj = 0; nj < 2; nj++)
            #pragma unroll
            for (int r = 0; r < 4; r++) oacc[mi][nj][r] = 0.0f;

    #pragma unroll
    for (int kk = 0; kk < 12; kk++) {
        uint32_t pa[2][4];
        #pragma unroll
        for (int mi = 0; mi < 2; mi++) {
            const float* ap = &sm[WS_OFF + (rowA0 + mi * 16 + g) * WS_STRIDE + kk * 8 + tg];
            pa[mi][0] = __float_as_uint(ap[0]);
            pa[mi][1] = __float_as_uint(ap[8 * WS_STRIDE]);
            pa[mi][2] = __float_as_uint(ap[4]);
            pa[mi][3] = __float_as_uint(ap[8 * WS_STRIDE + 4]);
        }
        #pragma unroll
        for (int nj = 0; nj < 2; nj++) {
            // B[k=s][n=h] = v[s][h]; vs is [s][h] row-major
            const float* bp = &sm[VS_OFF + (kk * 8 + tg) * VS_STRIDE + nq * 16 + nj * 8 + g];
            uint32_t bfrag[2] = { __float_as_uint(bp[0]),
                                  __float_as_uint(bp[4 * VS_STRIDE]) };
            mma_tf32(oacc[0][nj], pa[0], bfrag);
            mma_tf32(oacc[1][nj], pa[1], bfrag);
        }
    }

    // ---------- store output ----------
    float* ob = out + (size_t)b * Tq * Hd;
    #pragma unroll
    for (int mi = 0; mi < 2; mi++)
        #pragma unroll
        for (int nj = 0; nj < 2; nj++) {
            int n    = nq * 16 + nj * 8 + 2 * tg;
            int row0 = rowA0 + mi * 16 + g;
            *(float2*)&ob[row0 * Hd + n] =
                make_float2(oacc[mi][nj][0], oacc[mi][nj][1]);
            *(float2*)&ob[(row0 + 8) * Hd + n] =
                make_float2(oacc[mi][nj][2], oacc[mi][nj][3]);
        }
}

extern "C" void kernel_launch(void* const* d_in, const int* in_sizes, int n_in,
                              void* d_out, int out_size) {
    const float* x  = (const float*)d_in[0];
    const float* Wk = (const float*)d_in[1];
    const float* Wq = (const float*)d_in[2];
    const float* Wv = (const float*)d_in[3];
    float* out = (float*)d_out;

    cudaFuncSetAttribute(head_attn_kernel,
                         cudaFuncAttributeMaxDynamicSharedMemorySize, SMEM_BYTES);
    head_attn_kernel<<<4096, 384, SMEM_BYTES>>>(x, Wk, Wq, Wv, out);
}

// round 5
// speedup vs baseline: 1.0894x; 1.0894x over previous
#include <cuda_runtime.h>
#include <cstdint>

// Fused causal single-head attention, one CTA per batch element.
// B=4096, T=96, C=256, H=64.  tf32 mma.sync (m16n8k8), fp32 accumulate.
//
// R4 changes vs R3:
//  * x is streamed in k=32 chunks (double-buffered) like W -> smem 202KB -> 78KB
//  * score matrix WS overlays q/k (dead after QK^T MMA)     -> 2 CTAs/SM
//  * tf32 rounding moved from smem passes to fragment regs  -> ~40% less LDS traffic
//  * __launch_bounds__(384, 2) to force 2-CTA occupancy

namespace {
constexpr int Tq = 96;
constexpr int Cd = 256;
constexpr int Hd = 64;

constexpr int KC = 32;           // phase-1 k-chunk

// padded smem strides (floats), conflict-free for the fragment patterns used
constexpr int XS_STRIDE = 36;    // bank = (4*row + col) % 32 over 8 rows x 4 cols
constexpr int WC_STRIDE = 200;   // bank = (8*tg + g) % 32
constexpr int QS_STRIDE = 68;
constexpr int KS_STRIDE = 68;
constexpr int VS_STRIDE = 72;    // bank = (8*tg + g) % 32
constexpr int WS_STRIDE = 100;   // bank = (4*row + col) % 32

// phase-1 streaming layout (floats)
constexpr int XS0_OFF = 0;                          // 96*36 = 3456
constexpr int XS1_OFF = XS0_OFF + Tq * XS_STRIDE;   // 3456
constexpr int WC0_OFF = XS1_OFF + Tq * XS_STRIDE;   // 6912  (32*200 = 6400)
constexpr int WC1_OFF = WC0_OFF + KC * WC_STRIDE;   // 13312
constexpr int P1_END  = WC1_OFF + KC * WC_STRIDE;   // 19712

// phase-2/3 overlay (phase-1 buffers dead at scatter time)
constexpr int QS_OFF = 0;                           // 96*68 = 6528
constexpr int KS_OFF = QS_OFF + Tq * QS_STRIDE;     // 6528
constexpr int VS_OFF = KS_OFF + Tq * KS_STRIDE;     // 13056, 96*72=6912 -> ends 19968
constexpr int WS_OFF = 0;                           // overlays q/k AFTER QK^T MMA; 96*100=9600 < VS_OFF

constexpr int SMEM_FLOATS = (P1_END > VS_OFF + Tq * VS_STRIDE)
                            ? P1_END : (VS_OFF + Tq * VS_STRIDE);   // 19968
constexpr int SMEM_BYTES = SMEM_FLOATS * 4;                         // 79872 B
}

__device__ __forceinline__ uint32_t tf32u(float f) {
    uint32_t u;
    asm("cvt.rna.tf32.f32 %0, %1;" : "=r"(u) : "f"(f));
    return u;
}
__device__ __forceinline__ float tf32r(float f) {
    return __uint_as_float(tf32u(f));
}

__device__ __forceinline__ void mma_tf32(float* acc, const uint32_t* a, const uint32_t* b) {
    asm volatile(
        "mma.sync.aligned.m16n8k8.row.col.f32.tf32.tf32.f32 "
        "{%0,%1,%2,%3}, {%4,%5,%6,%7}, {%8,%9}, {%0,%1,%2,%3};"
        : "+f"(acc[0]), "+f"(acc[1]), "+f"(acc[2]), "+f"(acc[3])
        : "r"(a[0]), "r"(a[1]), "r"(a[2]), "r"(a[3]), "r"(b[0]), "r"(b[1]));
}

__device__ __forceinline__ void cp16(float* smem_dst, const float* gsrc) {
    uint32_t s = (uint32_t)__cvta_generic_to_shared(smem_dst);
    asm volatile("cp.async.cg.shared.global [%0], [%1], 16;" :: "r"(s), "l"(gsrc));
}
#define CP_COMMIT() asm volatile("cp.async.commit_group;")
#define CP_WAIT(n)  asm volatile("cp.async.wait_group %0;" :: "n"(n))

__global__ __launch_bounds__(384, 2)
void head_attn_kernel(const float* __restrict__ x,
                      const float* __restrict__ Wk,
                      const float* __restrict__ Wq,
                      const float* __restrict__ Wv,
                      float* __restrict__ out) {
    extern __shared__ float sm[];
    const int b    = blockIdx.x;
    const int tid  = threadIdx.x;
    const int wid  = tid >> 5;
    const int lane = tid & 31;
    const int g    = lane >> 2;   // groupID (row within fragment)
    const int tg   = lane & 3;    // thread-in-group (col within fragment)

    const int mtp  = wid >> 2;    // 0..2 -> rows [mtp*32, mtp*32+32)
    const int nq   = wid & 3;     // 0..3 -> n quarter
    const int rowA0 = mtp * 32;

    const float* xb = x + (size_t)b * Tq * Cd;

    // ---- chunk loaders: chunk c covers k rows [c*32, c*32+32) ----
    auto load_x = [&](int c, int off) {
        #pragma unroll
        for (int i = tid; i < Tq * (KC / 4); i += 384) {  // 768 float4
            int row = i >> 3;
            int c4  = i & 7;
            cp16(&sm[off + row * XS_STRIDE + c4 * 4], xb + row * Cd + c * KC + c4 * 4);
        }
    };
    auto load_w = [&](int c, int off) {
        #pragma unroll
        for (int i = tid; i < KC * 48; i += 384) {        // 1536 float4
            int row = i / 48;
            int seg = i % 48;
            int w   = seg >> 4;                           // 0=q,1=k,2=v
            int c4  = seg & 15;
            const float* src = (w == 0 ? Wq : (w == 1 ? Wk : Wv))
                               + (size_t)(c * KC + row) * Hd + c4 * 4;
            cp16(&sm[off + row * WC_STRIDE + w * 64 + c4 * 4], src);
        }
    };

    load_x(0, XS0_OFF); load_w(0, WC0_OFF); CP_COMMIT();
    load_x(1, XS1_OFF); load_w(1, WC1_OFF); CP_COMMIT();

    // ---------- phase 1: qkv = x @ [Wq|Wk|Wv], 8 chunks of k=32 ----------
    float acc[2][6][4];
    #pragma unroll
    for (int mi = 0; mi < 2; mi++)
        #pragma unroll
        for (int nj = 0; nj < 6; nj++)
            #pragma unroll
            for (int r = 0; r < 4; r++) acc[mi][nj][r] = 0.0f;

    auto compute_chunk = [&](int xoff, int woff) {
        #pragma unroll
        for (int kk = 0; kk < 4; kk++) {
            uint32_t afrag[2][4];
            #pragma unroll
            for (int mi = 0; mi < 2; mi++) {
                const float* ap = &sm[xoff + (rowA0 + mi * 16 + g) * XS_STRIDE
                                      + kk * 8 + tg];
                afrag[mi][0] = tf32u(ap[0]);
                afrag[mi][1] = tf32u(ap[8 * XS_STRIDE]);
                afrag[mi][2] = tf32u(ap[4]);
                afrag[mi][3] = tf32u(ap[8 * XS_STRIDE + 4]);
            }
            #pragma unroll
            for (int nj = 0; nj < 6; nj++) {
                const float* bp = &sm[woff + (kk * 8 + tg) * WC_STRIDE
                                      + nq * 48 + nj * 8 + g];
                uint32_t bfrag[2] = { tf32u(bp[0]), tf32u(bp[4 * WC_STRIDE]) };
                mma_tf32(acc[0][nj], afrag[0], bfrag);
                mma_tf32(acc[1][nj], afrag[1], bfrag);
            }
        }
    };

    #pragma unroll
    for (int c = 0; c < 8; c++) {
        if (c < 7) { CP_WAIT(1); } else { CP_WAIT(0); }
        __syncthreads();                 // chunk c visible to all
        const int xoff = (c & 1) ? XS1_OFF : XS0_OFF;
        const int woff = (c & 1) ? WC1_OFF : WC0_OFF;
        compute_chunk(xoff, woff);
        if (c + 2 < 8) {
            __syncthreads();             // everyone done reading this buffer
            load_x(c + 2, xoff);
            load_w(c + 2, woff);
            CP_COMMIT();
        }
    }
    __syncthreads();                     // phase-1 buffers dead; overlay begins

    // ---------- scatter qkv accumulators to smem (tf32-rounded) ----------
    auto qkv_ptr = [&](int row, int n) -> float* {
        if (n < 64)  return &sm[QS_OFF + row * QS_STRIDE + n];
        if (n < 128) return &sm[KS_OFF + row * KS_STRIDE + (n - 64)];
        return &sm[VS_OFF + row * VS_STRIDE + (n - 128)];
    };
    #pragma unroll
    for (int mi = 0; mi < 2; mi++)
        #pragma unroll
        for (int nj = 0; nj < 6; nj++) {
            int n    = nq * 48 + nj * 8 + 2 * tg;
            int row0 = rowA0 + mi * 16 + g;
            *(float2*)qkv_ptr(row0, n) =
                make_float2(tf32r(acc[mi][nj][0]), tf32r(acc[mi][nj][1]));
            *(float2*)qkv_ptr(row0 + 8, n) =
                make_float2(tf32r(acc[mi][nj][2]), tf32r(acc[mi][nj][3]));
        }
    __syncthreads();

    // ---------- phase 2: wei = q @ k^T (q/k already tf32-rounded) ----------
    float wacc[2][3][4];
    #pragma unroll
    for (int mi = 0; mi < 2; mi++)
        #pragma unroll
        for (int nj = 0; nj < 3; nj++)
            #pragma unroll
            for (int r = 0; r < 4; r++) wacc[mi][nj][r] = 0.0f;

    #pragma unroll
    for (int kk = 0; kk < 8; kk++) {
        uint32_t qa[2][4];
        #pragma unroll
        for (int mi = 0; mi < 2; mi++) {
            const float* ap = &sm[QS_OFF + (rowA0 + mi * 16 + g) * QS_STRIDE + kk * 8 + tg];
            qa[mi][0] = __float_as_uint(ap[0]);
            qa[mi][1] = __float_as_uint(ap[8 * QS_STRIDE]);
            qa[mi][2] = __float_as_uint(ap[4]);
            qa[mi][3] = __float_as_uint(ap[8 * QS_STRIDE + 4]);
        }
        #pragma unroll
        for (int nj = 0; nj < 3; nj++) {
            const float* bp = &sm[KS_OFF + (nq * 24 + nj * 8 + g) * KS_STRIDE + kk * 8 + tg];
            uint32_t bfrag[2] = { __float_as_uint(bp[0]), __float_as_uint(bp[4]) };
            mma_tf32(wacc[0][nj], qa[0], bfrag);
            mma_tf32(wacc[1][nj], qa[1], bfrag);
        }
    }
    __syncthreads();   // all q/k reads done before WS overlays them
    {
        const float scale = 0.0625f;  // C^-0.5
        #pragma unroll
        for (int mi = 0; mi < 2; mi++)
            #pragma unroll
            for (int nj = 0; nj < 3; nj++) {
                int n    = nq * 24 + nj * 8 + 2 * tg;
                int row0 = rowA0 + mi * 16 + g;
                float s00 = (n     <= row0) ? wacc[mi][nj][0] * scale : -1e30f;
                float s01 = (n + 1 <= row0) ? wacc[mi][nj][1] * scale : -1e30f;
                float s10 = (n     <= row0 + 8) ? wacc[mi][nj][2] * scale : -1e30f;
                float s11 = (n + 1 <= row0 + 8) ? wacc[mi][nj][3] * scale : -1e30f;
                *(float2*)&sm[WS_OFF + row0 * WS_STRIDE + n]       = make_float2(s00, s01);
                *(float2*)&sm[WS_OFF + (row0 + 8) * WS_STRIDE + n] = make_float2(s10, s11);
            }
    }
    __syncthreads();

    // ---------- softmax: warp w owns rows [8w, 8w+8); 4 lanes per row ----------
    {
        int r = wid * 8 + (lane >> 2);
        int i = lane & 3;
        float vb[24];
        float mx = -1e30f;
        #pragma unroll
        for (int j = 0; j < 24; j++) {
            vb[j] = sm[WS_OFF + r * WS_STRIDE + i + 4 * j];
            mx = fmaxf(mx, vb[j]);
        }
        mx = fmaxf(mx, __shfl_xor_sync(0xffffffffu, mx, 1));
        mx = fmaxf(mx, __shfl_xor_sync(0xffffffffu, mx, 2));
        float ssum = 0.0f;
        #pragma unroll
        for (int j = 0; j < 24; j++) {
            vb[j] = __expf(vb[j] - mx);
            ssum += vb[j];
        }
        ssum += __shfl_xor_sync(0xffffffffu, ssum, 1);
        ssum += __shfl_xor_sync(0xffffffffu, ssum, 2);
        float inv = 1.0f / ssum;
        #pragma unroll
        for (int j = 0; j < 24; j++)
            sm[WS_OFF + r * WS_STRIDE + i + 4 * j] = tf32r(vb[j] * inv);
    }
    __syncthreads();

    // ---------- phase 3: out = wei @ v ----------
    float oacc[2][2][4];
    #pragma unroll
    for (int mi = 0; mi < 2; mi++)
        #pragma unroll
        for (int nj = 0; nj < 2; nj++)
            #pragma unroll
            for (int r = 0; r < 4; r++) oacc[mi][nj][r] = 0.0f;

    #pragma unroll
    for (int kk = 0; kk < 12; kk++) {
        uint32_t pa[2][4];
        #pragma unroll
        for (int mi = 0; mi < 2; mi++) {
            const float* ap = &sm[WS_OFF + (rowA0 + mi * 16 + g) * WS_STRIDE + kk * 8 + tg];
            pa[mi][0] = __float_as_uint(ap[0]);
            pa[mi][1] = __float_as_uint(ap[8 * WS_STRIDE]);
            pa[mi][2] = __float_as_uint(ap[4]);
            pa[mi][3] = __float_as_uint(ap[8 * WS_STRIDE + 4]);
        }
        #pragma unroll
        for (int nj = 0; nj < 2; nj++) {
            const float* bp = &sm[VS_OFF + (kk * 8 + tg) * VS_STRIDE + nq * 16 + nj * 8 + g];
            uint32_t bfrag[2] = { __float_as_uint(bp[0]),
                                  __float_as_uint(bp[4 * VS_STRIDE]) };
            mma_tf32(oacc[0][nj], pa[0], bfrag);
            mma_tf32(oacc[1][nj], pa[1], bfrag);
        }
    }

    // ---------- store output ----------
    float* ob = out + (size_t)b * Tq * Hd;
    #pragma unroll
    for (int mi = 0; mi < 2; mi++)
        #pragma unroll
        for (int nj = 0; nj < 2; nj++) {
            int n    = nq * 16 + nj * 8 + 2 * tg;
            int row0 = rowA0 + mi * 16 + g;
            *(float2*)&ob[row0 * Hd + n] =
                make_float2(oacc[mi][nj][0], oacc[mi][nj][1]);
            *(float2*)&ob[(row0 + 8) * Hd + n] =
                make_float2(oacc[mi][nj][2], oacc[mi][nj][3]);
        }
}

extern "C" void kernel_launch(void* const* d_in, const int* in_sizes, int n_in,
                              void* d_out, int out_size) {
    const float* x  = (const float*)d_in[0];
    const float* Wk = (const float*)d_in[1];
    const float* Wq = (const float*)d_in[2];
    const float* Wv = (const float*)d_in[3];
    float* out = (float*)d_out;

    cudaFuncSetAttribute(head_attn_kernel,
                         cudaFuncAttributeMaxDynamicSharedMemorySize, SMEM_BYTES);
    head_attn_kernel<<<4096, 384, SMEM_BYTES>>>(x, Wk, Wq, Wv, out);
}